// round 7
// baseline (speedup 1.0000x reference)
#include <cuda_runtime.h>
#include <cuda_bf16.h>

// Problem constants
#define NB 256   // batch (both i and j axes)
#define ND 64    // dim_z
#define NS 32    // samples
#define NPOINTS_PER_D (NB * NS)          // 8192 (j,s) points per dim d
#define P 4                              // points per thread
#define THREADS 128
#define POINTS_PER_BLOCK (THREADS * P)   // 512
#define YTILES (NPOINTS_PER_D / POINTS_PER_BLOCK) // 16
#define GRID_TOTAL (ND * YTILES)         // 1024

__device__ __forceinline__ float ex2_approx(float x) {
    float r;
    asm("ex2.approx.ftz.f32 %0, %1;" : "=f"(r) : "f"(x));
    return r;
}

// Single-kernel deterministic reduction state. g_acc accumulates raw partial
// sums; the last block (ticket == GRID_TOTAL-1) writes the scaled result to
// d_out and resets g_acc to 0. atomicInc with limit GRID_TOTAL-1 self-wraps
// the ticket counter to 0, so every launch starts from the same state:
// deterministic, graph-replayable, no separate zeroing kernel.
__device__ float        g_acc   = 0.0f;
__device__ unsigned int g_count = 0u;

__global__ __launch_bounds__(THREADS, 16)
void kl_kernel(const float* __restrict__ prior_mean,
               const float* __restrict__ prior_logvar,
               const float* __restrict__ post_mean,
               const float* __restrict__ post_logvar,
               const float* __restrict__ eps,
               float* __restrict__ out)
{
    constexpr float LOG_2PI  = 1.8378770664093453f;
    constexpr float INV_LN2  = 1.4426950408889634f;
    constexpr float LOG_B    = 5.545177444479562f;   // ln(256)
    constexpr float VAR_EPS  = 1.0e-4f;

    // Per-posterior-i quadratic coefficients in base-2 domain:
    //   w_i(z) = a*z^2 + b*z + c,  a = -inv, b = 2*inv*m, c = c0 - inv*m^2
    // packed as float4 so the inner loop does ONE LDS.128 per i (uniform
    // index -> broadcast, conflict-free).
    __shared__ float4 sm_p[NB];
    __shared__ float  sm_red[THREADS / 32];

    const int d = blockIdx.x;
    const int t = threadIdx.x;

    // Load the 256 posterior (i) params for this dim d (2 per thread).
#pragma unroll
    for (int r = 0; r < NB / THREADS; r++) {
        int i = t + r * THREADS;
        float m   = post_mean[i * ND + d];
        float lv  = post_logvar[i * ND + d];
        float inv = INV_LN2 / (2.0f * __expf(lv) + VAR_EPS);
        float c0  = (-0.5f * LOG_2PI - 0.5f * lv) * INV_LN2;
        float4 pr;
        pr.x = -inv;
        pr.y = 2.0f * inv * m;
        pr.z = fmaf(-inv, m * m, c0);
        pr.w = 0.0f;
        sm_p[i] = pr;
    }
    __syncthreads();

    // Each thread owns P=4 sample points (j,s) for this d.
    const int qbase = blockIdx.y * POINTS_PER_BLOCK + t;

    float z[P];
    float acc[P];
#pragma unroll
    for (int p = 0; p < P; p++) {
        int q = qbase + p * THREADS;
        int j = q >> 5;        // q / NS
        int s = q & 31;        // q % NS
        float pmj  = post_mean[j * ND + d];
        float plvj = post_logvar[j * ND + d];
        float e    = eps[(j * ND + d) * NS + s];
        z[p]   = fmaf(e, __expf(0.5f * plvj), pmj);
        acc[p] = 0.0f;
    }

    // Main loop: sum_i 2^{w_i(z_p)}, unstabilized single pass.
    // Safe: w <= c0/ln2 ~ 1.6 (no overflow); the i==j diagonal term keeps
    // the sum >= ~e^-14 (no total underflow). This loop sits at ~98% of the
    // MUFU-pipe floor (4 EX2 per 8 SMSP-cycles) -- the hard roofline.
#pragma unroll 4
    for (int i = 0; i < NB; i++) {
        float4 pr = sm_p[i];
#pragma unroll
        for (int p = 0; p < P; p++) {
            float t0 = fmaf(z[p], pr.x, pr.y);
            float w  = fmaf(z[p], t0, pr.z);
            acc[p] += ex2_approx(w);
        }
    }

    // Epilogue: lse, prior log-density, density gap.
    float local = 0.0f;
#pragma unroll
    for (int p = 0; p < P; p++) {
        int q = qbase + p * THREADS;
        int j = q >> 5;
        float lse = __logf(acc[p]);   // ln(sum 2^w) = ln(sum e^v)

        float pm  = prior_mean[j * ND + d];
        float plv = prior_logvar[j * ND + d];
        float dd  = z[p] - pm;
        float logprior = -0.5f * LOG_2PI - 0.5f * plv
                         - dd * dd / (2.0f * __expf(plv) + VAR_EPS);

        local += (lse - LOG_B) - logprior;
    }

    // Block reduction.
#pragma unroll
    for (int off = 16; off > 0; off >>= 1)
        local += __shfl_xor_sync(0xffffffffu, local, off);

    int lane = t & 31, warp = t >> 5;
    if (lane == 0) sm_red[warp] = local;
    __syncthreads();
    if (warp == 0) {
        float v = (lane < THREADS / 32) ? sm_red[lane] : 0.0f;
#pragma unroll
        for (int off = 2; off > 0; off >>= 1)
            v += __shfl_xor_sync(0xffffffffu, v, off);

        if (lane == 0) {
            // Accumulate raw partial into the device-global accumulator.
            atomicAdd(&g_acc, v);
            __threadfence();
            // Ticket: atomicInc wraps to 0 at GRID_TOTAL-1, so the counter
            // is self-resetting across launches.
            unsigned int ticket = atomicInc(&g_count, GRID_TOTAL - 1u);
            if (ticket == GRID_TOTAL - 1u) {
                // All blocks' adds are visible (each fenced before its inc).
                __threadfence();
                float total = *((volatile float*)&g_acc);
                out[0] = total * (1.0f / (float)(NB * NS));
                // Reset accumulator for the next (graph-replayed) launch.
                *((volatile float*)&g_acc) = 0.0f;
                __threadfence();
            }
        }
    }
}

extern "C" void kernel_launch(void* const* d_in, const int* in_sizes, int n_in,
                              void* d_out, int out_size) {
    const float* prior_mean   = (const float*)d_in[0];
    const float* prior_logvar = (const float*)d_in[1];
    const float* post_mean    = (const float*)d_in[2];
    const float* post_logvar  = (const float*)d_in[3];
    const float* eps          = (const float*)d_in[4];
    float* out = (float*)d_out;

    dim3 grid(ND, YTILES);
    kl_kernel<<<grid, THREADS>>>(prior_mean, prior_logvar, post_mean,
                                 post_logvar, eps, out);
}

// round 8
// speedup vs baseline: 1.5339x; 1.5339x over previous
#include <cuda_runtime.h>
#include <cuda_bf16.h>

// Problem constants
#define NB 256   // batch (both i and j axes)
#define ND 64    // dim_z
#define NS 32    // samples
#define NPOINTS_PER_D (NB * NS)          // 8192 (j,s) points per dim d
#define P 4                              // points per thread
#define THREADS 128
#define POINTS_PER_BLOCK (THREADS * P)   // 512
#define YTILES (NPOINTS_PER_D / POINTS_PER_BLOCK) // 16
#define GRID_TOTAL (ND * YTILES)         // 1024

__device__ __forceinline__ float ex2_approx(float x) {
    float r;
    asm("ex2.approx.ftz.f32 %0, %1;" : "=f"(r) : "f"(x));
    return r;
}

// Single-launch reduction state. Every launch overwrites all GRID_TOTAL slots
// before any read (guaranteed by the ticket ordering), so no zero-init kernel
// is needed. The ticket counter self-wraps to 0 at GRID_TOTAL-1, so state is
// identical at the start of every (graph-replayed) launch. No membar/threadfence:
// release-store + acq_rel ticket provides the ordering; __ldcg bypasses L1 so
// no stale lines.
__device__ float        g_part[GRID_TOTAL];
__device__ unsigned int g_count = 0u;

__global__ __launch_bounds__(THREADS, 12)
void kl_kernel(const float* __restrict__ prior_mean,
               const float* __restrict__ prior_logvar,
               const float* __restrict__ post_mean,
               const float* __restrict__ post_logvar,
               const float* __restrict__ eps,
               float* __restrict__ out)
{
    constexpr float LOG_2PI  = 1.8378770664093453f;
    constexpr float INV_LN2  = 1.4426950408889634f;
    constexpr float LOG_B    = 5.545177444479562f;   // ln(256)
    constexpr float VAR_EPS  = 1.0e-4f;

    // Per-posterior-i quadratic coefficients in base-2 domain:
    //   w_i(z) = a*z^2 + b*z + c,  a = -inv, b = 2*inv*m, c = c0 - inv*m^2
    // packed as float4: ONE LDS.128 per i, uniform index -> broadcast.
    __shared__ float4 sm_p[NB];
    __shared__ float  sm_red[THREADS / 32];

    const int d = blockIdx.x;
    const int t = threadIdx.x;

    // Load the 256 posterior (i) params for this dim d (2 per thread).
#pragma unroll
    for (int r = 0; r < NB / THREADS; r++) {
        int i = t + r * THREADS;
        float m   = post_mean[i * ND + d];
        float lv  = post_logvar[i * ND + d];
        float inv = INV_LN2 / (2.0f * __expf(lv) + VAR_EPS);
        float c0  = (-0.5f * LOG_2PI - 0.5f * lv) * INV_LN2;
        float4 pr;
        pr.x = -inv;
        pr.y = 2.0f * inv * m;
        pr.z = fmaf(-inv, m * m, c0);
        pr.w = 0.0f;
        sm_p[i] = pr;
    }
    __syncthreads();

    // Each thread owns P=4 sample points (j,s) for this d.
    const int qbase = blockIdx.y * POINTS_PER_BLOCK + t;

    float z[P];
    float acc[P];
#pragma unroll
    for (int p = 0; p < P; p++) {
        int q = qbase + p * THREADS;
        int j = q >> 5;        // q / NS
        int s = q & 31;        // q % NS
        float pmj  = post_mean[j * ND + d];
        float plvj = post_logvar[j * ND + d];
        float e    = eps[(j * ND + d) * NS + s];
        z[p]   = fmaf(e, __expf(0.5f * plvj), pmj);
        acc[p] = 0.0f;
    }

    // Main loop: sum_i 2^{w_i(z_p)}, unstabilized single pass.
    // Safe: w <= c0/ln2 ~ 1.6 (no overflow); the i==j diagonal term keeps
    // the sum >= ~e^-14 (no total underflow). Sits at ~98% of the MUFU
    // floor (4 EX2 per 8 SMSP-cycles) -- the hard roofline.
#pragma unroll 4
    for (int i = 0; i < NB; i++) {
        float4 pr = sm_p[i];
#pragma unroll
        for (int p = 0; p < P; p++) {
            float t0 = fmaf(z[p], pr.x, pr.y);
            float w  = fmaf(z[p], t0, pr.z);
            acc[p] += ex2_approx(w);
        }
    }

    // Epilogue: lse, prior log-density, density gap.
    float local = 0.0f;
#pragma unroll
    for (int p = 0; p < P; p++) {
        int q = qbase + p * THREADS;
        int j = q >> 5;
        float lse = __logf(acc[p]);   // ln(sum 2^w) = ln(sum e^v)

        float pm  = prior_mean[j * ND + d];
        float plv = prior_logvar[j * ND + d];
        float dd  = z[p] - pm;
        float logprior = -0.5f * LOG_2PI - 0.5f * plv
                         - dd * dd / (2.0f * __expf(plv) + VAR_EPS);

        local += (lse - LOG_B) - logprior;
    }

    // Block reduction.
#pragma unroll
    for (int off = 16; off > 0; off >>= 1)
        local += __shfl_xor_sync(0xffffffffu, local, off);

    int lane = t & 31, warp = t >> 5;
    if (lane == 0) sm_red[warp] = local;
    __syncthreads();

    if (warp == 0) {
        float v = (lane < THREADS / 32) ? sm_red[lane] : 0.0f;
#pragma unroll
        for (int off = 2; off > 0; off >>= 1)
            v += __shfl_xor_sync(0xffffffffu, v, off);

        const int bid = blockIdx.y * ND + blockIdx.x;   // 0..GRID_TOTAL-1

        unsigned int is_last = 0u;
        if (lane == 0) {
            // Publish this block's raw partial (release: visible at GPU scope
            // before the ticket increment below).
            asm volatile("st.release.gpu.f32 [%0], %1;"
                         :: "l"(&g_part[bid]), "f"(v) : "memory");
            // Ticket (acq_rel): wraps to 0 at GRID_TOTAL-1 -> self-resetting.
            unsigned int ticket;
            asm volatile("atom.acq_rel.gpu.inc.u32 %0, [%1], %2;"
                         : "=r"(ticket)
                         : "l"(&g_count), "r"((unsigned)(GRID_TOTAL - 1))
                         : "memory");
            is_last = (ticket == (unsigned)(GRID_TOTAL - 1)) ? 1u : 0u;
        }
        // Broadcast "last block" flag to the whole warp.
        is_last = __shfl_sync(0xffffffffu, is_last, 0);

        if (is_last) {
            // All 1024 release-stores happened-before our acq_rel ticket read.
            // Fixed-order reduction (deterministic). __ldcg bypasses L1.
            float s = 0.0f;
#pragma unroll
            for (int r = 0; r < GRID_TOTAL / 32; r++)
                s += __ldcg(&g_part[lane + r * 32]);
#pragma unroll
            for (int off = 16; off > 0; off >>= 1)
                s += __shfl_xor_sync(0xffffffffu, s, off);
            if (lane == 0)
                out[0] = s * (1.0f / (float)(NB * NS));
        }
    }
}

extern "C" void kernel_launch(void* const* d_in, const int* in_sizes, int n_in,
                              void* d_out, int out_size) {
    const float* prior_mean   = (const float*)d_in[0];
    const float* prior_logvar = (const float*)d_in[1];
    const float* post_mean    = (const float*)d_in[2];
    const float* post_logvar  = (const float*)d_in[3];
    const float* eps          = (const float*)d_in[4];
    float* out = (float*)d_out;

    dim3 grid(ND, YTILES);
    kl_kernel<<<grid, THREADS>>>(prior_mean, prior_logvar, post_mean,
                                 post_logvar, eps, out);
}